// round 4
// baseline (speedup 1.0000x reference)
#include <cuda_runtime.h>
#include <cuda_bf16.h>
#include <cstdint>
#include <cstdio>

// Problem constants
#define B_  2
#define S_  2048
#define C_  1024
#define H_  16
#define HD_ 64
#define M_  (B_ * S_)      // 4096 rows
#define FF_ (4 * C_)       // 4096
#define V_  32000

// ---------------------------------------------------------------------------
// Scratch (device globals — allocation inside kernel_launch is forbidden)
// ---------------------------------------------------------------------------
__device__ float g_x  [M_ * C_];
__device__ float g_wq [C_ * C_];
__device__ float g_wk [C_ * C_];
__device__ float g_wv [C_ * C_];
__device__ float g_q  [M_ * C_];
__device__ float g_k  [M_ * C_];
__device__ float g_v  [M_ * C_];
__device__ float g_o  [M_ * C_];
__device__ float g_x2 [M_ * C_];
__device__ float g_h1 [M_ * FF_];
__device__ float g_x3 [M_ * C_];

// ---------------------------------------------------------------------------
// Embedding
// ---------------------------------------------------------------------------
__global__ void embed_kernel(const int* __restrict__ idx,
                             const float* __restrict__ tok,
                             const float* __restrict__ pos,
                             float* __restrict__ x)
{
    int i = blockIdx.x * blockDim.x + threadIdx.x;
    int c  = i & (C_ - 1);
    int bs = i >> 10;
    int s  = bs & (S_ - 1);
    x[i] = tok[(size_t)idx[bs] * C_ + c] + pos[(size_t)s * C_ + c];
}

// ---------------------------------------------------------------------------
// Pack W[h][c][d] -> Wp[c][h*HD+d]
// ---------------------------------------------------------------------------
__global__ void pack_w_kernel(const float* __restrict__ W, float* __restrict__ Wp)
{
    int i = blockIdx.x * blockDim.x + threadIdx.x;
    int c  = i >> 10;
    int hd = i & (C_ - 1);
    int h  = hd >> 6;
    int d  = hd & (HD_ - 1);
    Wp[i] = W[((size_t)h * C_ + c) * HD_ + d];
}

// ---------------------------------------------------------------------------
// 3xTF32 tensor-core GEMM: C = A[M,K] @ B[K,N] (+bias)(+relu)
// Block 128x128, BK=16, 256 threads = 8 warps (2x4), warp tile 64x32.
// Per warp: 4x4 m16n8k8 mma tiles. hi/lo split for fp32-level accuracy:
//   acc += Ah*Bh + Ah*Bl + Al*Bh
// ---------------------------------------------------------------------------
#define BM 128
#define BN 128
#define BK 16
#define PITCH 136   // words; (k*136 + m) % 32 = k*8 + m%32 -> conflict-free frags

__device__ __forceinline__ uint32_t f2tf32(float v)
{
    uint32_t r;
    asm("cvt.rna.tf32.f32 %0, %1;" : "=r"(r) : "f"(v));
    return r;
}

__device__ __forceinline__ void mma_tf32(float* c, const uint32_t* a, const uint32_t* b)
{
    asm volatile(
        "mma.sync.aligned.m16n8k8.row.col.f32.tf32.tf32.f32 "
        "{%0,%1,%2,%3}, {%4,%5,%6,%7}, {%8,%9}, {%0,%1,%2,%3};"
        : "+f"(c[0]), "+f"(c[1]), "+f"(c[2]), "+f"(c[3])
        : "r"(a[0]), "r"(a[1]), "r"(a[2]), "r"(a[3]),
          "r"(b[0]), "r"(b[1]));
}

template<bool RELU, bool BIAS>
__global__ __launch_bounds__(256)
void gemm_tf32_kernel(const float* __restrict__ A, const float* __restrict__ Bm,
                      const float* __restrict__ bias, float* __restrict__ Cm,
                      int M, int N, int K)
{
    __shared__ uint32_t As_hi[BK * PITCH];
    __shared__ uint32_t As_lo[BK * PITCH];
    __shared__ uint32_t Bs_hi[BK * PITCH];
    __shared__ uint32_t Bs_lo[BK * PITCH];

    const int tid    = threadIdx.x;
    const int lane   = tid & 31;
    const int gid    = lane >> 2;        // 0..7
    const int tig    = lane & 3;         // 0..3
    const int warp   = tid >> 5;         // 0..7
    const int warp_m = warp >> 2;        // 0..1  (64-row slabs)
    const int warp_n = warp & 3;         // 0..3  (32-col slabs)

    const int bm = blockIdx.y * BM;
    const int bn = blockIdx.x * BN;

    float acc[4][4][4];                  // [mt][nt][frag]
#pragma unroll
    for (int mt = 0; mt < 4; mt++)
#pragma unroll
        for (int nt = 0; nt < 4; nt++)
#pragma unroll
            for (int i = 0; i < 4; i++) acc[mt][nt][i] = 0.f;

    const float* Ap = A + (size_t)bm * K;
    const int a_r0  = tid >> 2;          // 0..63
    const int a_col = (tid & 3) * 4;     // 0,4,8,12
    const int b_k0  = tid >> 5;          // 0..7
    const int b_col = (tid & 31) * 4;    // 0..124

    for (int k0 = 0; k0 < K; k0 += BK) {
        // ---- load + split A tile (transpose to As[k][m]) ----
#pragma unroll
        for (int p = 0; p < 2; p++) {
            int r = a_r0 + p * 64;
            float4 v = *(const float4*)(Ap + (size_t)r * K + k0 + a_col);
            float f[4] = {v.x, v.y, v.z, v.w};
#pragma unroll
            for (int i = 0; i < 4; i++) {
                uint32_t h = f2tf32(f[i]);
                uint32_t l = f2tf32(f[i] - __uint_as_float(h));
                As_hi[(a_col + i) * PITCH + r] = h;
                As_lo[(a_col + i) * PITCH + r] = l;
            }
        }
        // ---- load + split B tile (Bs[k][n]) ----
#pragma unroll
        for (int p = 0; p < 2; p++) {
            int kr = b_k0 + p * 8;
            float4 v = *(const float4*)(Bm + (size_t)(k0 + kr) * N + bn + b_col);
            float f[4] = {v.x, v.y, v.z, v.w};
            uint4 hv, lv;
            uint32_t* hp = (uint32_t*)&hv;
            uint32_t* lp = (uint32_t*)&lv;
#pragma unroll
            for (int i = 0; i < 4; i++) {
                hp[i] = f2tf32(f[i]);
                lp[i] = f2tf32(f[i] - __uint_as_float(hp[i]));
            }
            *(uint4*)&Bs_hi[kr * PITCH + b_col] = hv;
            *(uint4*)&Bs_lo[kr * PITCH + b_col] = lv;
        }
        __syncthreads();

        // ---- mma over the two k-steps of 8 ----
#pragma unroll
        for (int ks = 0; ks < 2; ks++) {
            const int kk = ks * 8;
            uint32_t Ah[4][4], Al[4][4], Bh[4][2], Bl[4][2];
#pragma unroll
            for (int mt = 0; mt < 4; mt++) {
                int r0 = warp_m * 64 + mt * 16 + gid;
                int kA0 = (kk + tig) * PITCH;
                int kA1 = (kk + tig + 4) * PITCH;
                Ah[mt][0] = As_hi[kA0 + r0];
                Ah[mt][1] = As_hi[kA0 + r0 + 8];
                Ah[mt][2] = As_hi[kA1 + r0];
                Ah[mt][3] = As_hi[kA1 + r0 + 8];
                Al[mt][0] = As_lo[kA0 + r0];
                Al[mt][1] = As_lo[kA0 + r0 + 8];
                Al[mt][2] = As_lo[kA1 + r0];
                Al[mt][3] = As_lo[kA1 + r0 + 8];
            }
#pragma unroll
            for (int nt = 0; nt < 4; nt++) {
                int c0 = warp_n * 32 + nt * 8 + gid;
                Bh[nt][0] = Bs_hi[(kk + tig) * PITCH + c0];
                Bh[nt][1] = Bs_hi[(kk + tig + 4) * PITCH + c0];
                Bl[nt][0] = Bs_lo[(kk + tig) * PITCH + c0];
                Bl[nt][1] = Bs_lo[(kk + tig + 4) * PITCH + c0];
            }
#pragma unroll
            for (int mt = 0; mt < 4; mt++)
#pragma unroll
                for (int nt = 0; nt < 4; nt++) {
                    mma_tf32(acc[mt][nt], Ah[mt], Bh[nt]);
                    mma_tf32(acc[mt][nt], Ah[mt], Bl[nt]);
                    mma_tf32(acc[mt][nt], Al[mt], Bh[nt]);
                }
        }
        __syncthreads();
    }

    // ---- epilogue ----
#pragma unroll
    for (int mt = 0; mt < 4; mt++) {
        int row0 = bm + warp_m * 64 + mt * 16 + gid;
        int row1 = row0 + 8;
#pragma unroll
        for (int nt = 0; nt < 4; nt++) {
            int col = bn + warp_n * 32 + nt * 8 + tig * 2;
            float b0 = 0.f, b1 = 0.f;
            if (BIAS) { b0 = bias[col]; b1 = bias[col + 1]; }
            float v0 = acc[mt][nt][0] + b0;
            float v1 = acc[mt][nt][1] + b1;
            float v2 = acc[mt][nt][2] + b0;
            float v3 = acc[mt][nt][3] + b1;
            if (RELU) {
                v0 = fmaxf(v0, 0.f); v1 = fmaxf(v1, 0.f);
                v2 = fmaxf(v2, 0.f); v3 = fmaxf(v3, 0.f);
            }
            *(float2*)(Cm + (size_t)row0 * N + col) = make_float2(v0, v1);
            *(float2*)(Cm + (size_t)row1 * N + col) = make_float2(v2, v3);
        }
    }
}

// ---------------------------------------------------------------------------
// Flash-style causal attention (unchanged from baseline).
// Grid: (S/64, B*H). 64 threads, one query row per thread.
// ---------------------------------------------------------------------------
__global__ __launch_bounds__(64)
void attn_kernel(const float* __restrict__ Q, const float* __restrict__ Kt,
                 const float* __restrict__ Vt, float* __restrict__ O)
{
    const int qt  = blockIdx.x;
    const int bh  = blockIdx.y;
    const int b   = bh >> 4;
    const int h   = bh & (H_ - 1);
    const int tid = threadIdx.x;
    const int qs  = qt * 64 + tid;

    const size_t base = (size_t)b * S_ * C_ + (size_t)h * HD_;

    float4 q4[16], acc4[16];
    const float4* qp = (const float4*)(Q + base + (size_t)qs * C_);
#pragma unroll
    for (int t = 0; t < 16; t++) {
        q4[t]   = qp[t];
        acc4[t] = make_float4(0.f, 0.f, 0.f, 0.f);
    }

    float m = -1e30f, l = 0.f;
    const float scale = 0.125f;

    __shared__ float4 KV4[64][16];
    __shared__ float  Ss[64][65];

    for (int jt = 0; jt <= qt; jt++) {
        const float* kp = Kt + base + (size_t)(jt * 64) * C_;
        for (int r = 0; r < 64; r++)
            ((float*)&KV4[r][0])[tid] = kp[(size_t)r * C_ + tid];
        __syncthreads();

        const int jmax = (jt == qt) ? tid : 63;
        float mt = -1e30f;
        for (int j = 0; j < 64; j++) {
            float s = -1e30f;
            if (j <= jmax) {
                float d = 0.f;
#pragma unroll
                for (int t = 0; t < 16; t++) {
                    float4 kk = KV4[j][t];
                    d += q4[t].x * kk.x + q4[t].y * kk.y +
                         q4[t].z * kk.z + q4[t].w * kk.w;
                }
                s = d * scale;
            }
            Ss[tid][j] = s;
            mt = fmaxf(mt, s);
        }

        float mnew = fmaxf(m, mt);
        float corr = __expf(m - mnew);
        l *= corr;
#pragma unroll
        for (int t = 0; t < 16; t++) {
            acc4[t].x *= corr; acc4[t].y *= corr;
            acc4[t].z *= corr; acc4[t].w *= corr;
        }
        float ps = 0.f;
        for (int j = 0; j <= jmax; j++) {
            float p = __expf(Ss[tid][j] - mnew);
            Ss[tid][j] = p;
            ps += p;
        }
        l += ps;
        m = mnew;
        __syncthreads();

        const float* vp = Vt + base + (size_t)(jt * 64) * C_;
        for (int r = 0; r < 64; r++)
            ((float*)&KV4[r][0])[tid] = vp[(size_t)r * C_ + tid];
        __syncthreads();

        for (int j = 0; j <= jmax; j++) {
            float p = Ss[tid][j];
#pragma unroll
            for (int t = 0; t < 16; t++) {
                float4 vv = KV4[j][t];
                acc4[t].x += p * vv.x; acc4[t].y += p * vv.y;
                acc4[t].z += p * vv.z; acc4[t].w += p * vv.w;
            }
        }
        __syncthreads();
    }

    const float inv = 1.f / l;
    float4* op = (float4*)(O + base + (size_t)qs * C_);
#pragma unroll
    for (int t = 0; t < 16; t++)
        op[t] = make_float4(acc4[t].x * inv, acc4[t].y * inv,
                            acc4[t].z * inv, acc4[t].w * inv);
}

// ---------------------------------------------------------------------------
// Launch
// ---------------------------------------------------------------------------
extern "C" void kernel_launch(void* const* d_in, const int* in_sizes, int n_in,
                              void* d_out, int out_size)
{
    const int*   idx   = (const int*)  d_in[0];
    const float* tok   = (const float*)d_in[1];
    const float* pos   = (const float*)d_in[2];
    const float* Wq    = (const float*)d_in[3];
    const float* Wk    = (const float*)d_in[4];
    const float* Wv    = (const float*)d_in[5];
    const float* Wproj = (const float*)d_in[6];
    const float* bproj = (const float*)d_in[7];
    const float* W1    = (const float*)d_in[8];
    const float* b1    = (const float*)d_in[9];
    const float* W2    = (const float*)d_in[10];
    const float* b2    = (const float*)d_in[11];
    const float* Wlm   = (const float*)d_in[12];
    const float* blm   = (const float*)d_in[13];
    float*       out   = (float*)d_out;

    float *x, *wq, *wk, *wv, *q, *k, *v, *o, *x2, *h1, *x3;
    cudaGetSymbolAddress((void**)&x,  g_x);
    cudaGetSymbolAddress((void**)&wq, g_wq);
    cudaGetSymbolAddress((void**)&wk, g_wk);
    cudaGetSymbolAddress((void**)&wv, g_wv);
    cudaGetSymbolAddress((void**)&q,  g_q);
    cudaGetSymbolAddress((void**)&k,  g_k);
    cudaGetSymbolAddress((void**)&v,  g_v);
    cudaGetSymbolAddress((void**)&o,  g_o);
    cudaGetSymbolAddress((void**)&x2, g_x2);
    cudaGetSymbolAddress((void**)&h1, g_h1);
    cudaGetSymbolAddress((void**)&x3, g_x3);

    // 1. pack QKV weights
    {
        int n = C_ * C_;
        pack_w_kernel<<<n / 256, 256>>>(Wq, wq);
        pack_w_kernel<<<n / 256, 256>>>(Wk, wk);
        pack_w_kernel<<<n / 256, 256>>>(Wv, wv);
    }

    // 2. embedding
    embed_kernel<<<(M_ * C_) / 256, 256>>>(idx, tok, pos, x);

    // 3. Q, K, V projections
    {
        dim3 grid(C_ / BN, M_ / BM);
        gemm_tf32_kernel<false, false><<<grid, 256>>>(x, wq, nullptr, q, M_, C_, C_);
        gemm_tf32_kernel<false, false><<<grid, 256>>>(x, wk, nullptr, k, M_, C_, C_);
        gemm_tf32_kernel<false, false><<<grid, 256>>>(x, wv, nullptr, v, M_, C_, C_);
    }

    // 4. causal attention
    {
        dim3 grid(S_ / 64, B_ * H_);
        attn_kernel<<<grid, 64>>>(q, k, v, o);
    }

    // 5. output projection
    {
        dim3 grid(C_ / BN, M_ / BM);
        gemm_tf32_kernel<false, true><<<grid, 256>>>(o, Wproj, bproj, x2, M_, C_, C_);
    }

    // 6. MLP
    {
        dim3 grid1(FF_ / BN, M_ / BM);
        gemm_tf32_kernel<true, true><<<grid1, 256>>>(x2, W1, b1, h1, M_, FF_, C_);
        dim3 grid2(C_ / BN, M_ / BM);
        gemm_tf32_kernel<false, true><<<grid2, 256>>>(h1, W2, b2, x3, M_, C_, FF_);
    }

    // 7. LM head
    {
        dim3 grid(V_ / BN, M_ / BM);
        gemm_tf32_kernel<false, true><<<grid, 256>>>(x3, Wlm, blm, out, M_, V_, C_);
    }
}

// round 15
// speedup vs baseline: 1.6668x; 1.6668x over previous
#include <cuda_runtime.h>
#include <cuda_bf16.h>
#include <cstdint>
#include <cstdio>

// Problem constants
#define B_  2
#define S_  2048
#define C_  1024
#define H_  16
#define HD_ 64
#define M_  (B_ * S_)      // 4096 rows
#define FF_ (4 * C_)       // 4096
#define V_  32000

// ---------------------------------------------------------------------------
// Scratch (device globals)
// ---------------------------------------------------------------------------
__device__ float g_x  [M_ * C_];
__device__ float g_wq [C_ * C_];
__device__ float g_wk [C_ * C_];
__device__ float g_wv [C_ * C_];
__device__ float g_q  [M_ * C_];
__device__ float g_k  [M_ * C_];
__device__ float g_v  [M_ * C_];
__device__ float g_o  [M_ * C_];
__device__ float g_x2 [M_ * C_];
__device__ float g_h1 [M_ * FF_];
__device__ float g_x3 [M_ * C_];

// ---------------------------------------------------------------------------
// Embedding
// ---------------------------------------------------------------------------
__global__ void embed_kernel(const int* __restrict__ idx,
                             const float* __restrict__ tok,
                             const float* __restrict__ pos,
                             float* __restrict__ x)
{
    int i = blockIdx.x * blockDim.x + threadIdx.x;
    int c  = i & (C_ - 1);
    int bs = i >> 10;
    int s  = bs & (S_ - 1);
    x[i] = tok[(size_t)idx[bs] * C_ + c] + pos[(size_t)s * C_ + c];
}

// ---------------------------------------------------------------------------
// Pack W[h][c][d] -> Wp[c][h*HD+d]
// ---------------------------------------------------------------------------
__global__ void pack_w_kernel(const float* __restrict__ W, float* __restrict__ Wp)
{
    int i = blockIdx.x * blockDim.x + threadIdx.x;
    int c  = i >> 10;
    int hd = i & (C_ - 1);
    int h  = hd >> 6;
    int d  = hd & (HD_ - 1);
    Wp[i] = W[((size_t)h * C_ + c) * HD_ + d];
}

// ---------------------------------------------------------------------------
// Single-pass TF32 tensor-core GEMM: C = A[M,K] @ B[K,N] (+bias)(+relu)
// Block 128x128, BK=16, 256 threads = 8 warps (2x4), warp tile 64x32,
// 4x4 m16n8k8 mma tiles per warp.
// ---------------------------------------------------------------------------
#define BM 128
#define BN 128
#define BK 16
#define PITCH 136   // words; conflict-free fragment reads

__device__ __forceinline__ uint32_t f2tf32(float v)
{
    uint32_t r;
    asm("cvt.rna.tf32.f32 %0, %1;" : "=r"(r) : "f"(v));
    return r;
}

__device__ __forceinline__ void mma_tf32(float* c, const uint32_t* a, const uint32_t* b)
{
    asm volatile(
        "mma.sync.aligned.m16n8k8.row.col.f32.tf32.tf32.f32 "
        "{%0,%1,%2,%3}, {%4,%5,%6,%7}, {%8,%9}, {%0,%1,%2,%3};"
        : "+f"(c[0]), "+f"(c[1]), "+f"(c[2]), "+f"(c[3])
        : "r"(a[0]), "r"(a[1]), "r"(a[2]), "r"(a[3]),
          "r"(b[0]), "r"(b[1]));
}

template<bool RELU, bool BIAS>
__global__ __launch_bounds__(256)
void gemm_tf32_kernel(const float* __restrict__ A, const float* __restrict__ Bm,
                      const float* __restrict__ bias, float* __restrict__ Cm,
                      int M, int N, int K)
{
    __shared__ uint32_t As[BK * PITCH];
    __shared__ uint32_t Bs[BK * PITCH];

    const int tid    = threadIdx.x;
    const int lane   = tid & 31;
    const int gid    = lane >> 2;        // 0..7
    const int tig    = lane & 3;         // 0..3
    const int warp   = tid >> 5;         // 0..7
    const int warp_m = warp >> 2;        // 0..1
    const int warp_n = warp & 3;         // 0..3

    const int bm = blockIdx.y * BM;
    const int bn = blockIdx.x * BN;

    float acc[4][4][4];
#pragma unroll
    for (int mt = 0; mt < 4; mt++)
#pragma unroll
        for (int nt = 0; nt < 4; nt++)
#pragma unroll
            for (int i = 0; i < 4; i++) acc[mt][nt][i] = 0.f;

    const float* Ap = A + (size_t)bm * K;
    const int a_r0  = tid >> 2;          // 0..63
    const int a_col = (tid & 3) * 4;     // 0,4,8,12
    const int b_k0  = tid >> 5;          // 0..7
    const int b_col = (tid & 31) * 4;    // 0..124

    for (int k0 = 0; k0 < K; k0 += BK) {
        // A tile: transpose to As[k][m], tf32-converted
#pragma unroll
        for (int p = 0; p < 2; p++) {
            int r = a_r0 + p * 64;
            float4 v = *(const float4*)(Ap + (size_t)r * K + k0 + a_col);
            As[(a_col + 0) * PITCH + r] = f2tf32(v.x);
            As[(a_col + 1) * PITCH + r] = f2tf32(v.y);
            As[(a_col + 2) * PITCH + r] = f2tf32(v.z);
            As[(a_col + 3) * PITCH + r] = f2tf32(v.w);
        }
        // B tile: Bs[k][n]
#pragma unroll
        for (int p = 0; p < 2; p++) {
            int kr = b_k0 + p * 8;
            float4 v = *(const float4*)(Bm + (size_t)(k0 + kr) * N + bn + b_col);
            uint4 hv;
            hv.x = f2tf32(v.x); hv.y = f2tf32(v.y);
            hv.z = f2tf32(v.z); hv.w = f2tf32(v.w);
            *(uint4*)&Bs[kr * PITCH + b_col] = hv;
        }
        __syncthreads();

#pragma unroll
        for (int ks = 0; ks < 2; ks++) {
            const int kk = ks * 8;
            uint32_t Ah[4][4], Bh[4][2];
#pragma unroll
            for (int mt = 0; mt < 4; mt++) {
                int r0  = warp_m * 64 + mt * 16 + gid;
                int kA0 = (kk + tig) * PITCH;
                int kA1 = (kk + tig + 4) * PITCH;
                Ah[mt][0] = As[kA0 + r0];
                Ah[mt][1] = As[kA0 + r0 + 8];
                Ah[mt][2] = As[kA1 + r0];
                Ah[mt][3] = As[kA1 + r0 + 8];
            }
#pragma unroll
            for (int nt = 0; nt < 4; nt++) {
                int c0 = warp_n * 32 + nt * 8 + gid;
                Bh[nt][0] = Bs[(kk + tig) * PITCH + c0];
                Bh[nt][1] = Bs[(kk + tig + 4) * PITCH + c0];
            }
#pragma unroll
            for (int mt = 0; mt < 4; mt++)
#pragma unroll
                for (int nt = 0; nt < 4; nt++)
                    mma_tf32(acc[mt][nt], Ah[mt], Bh[nt]);
        }
        __syncthreads();
    }

    // epilogue
#pragma unroll
    for (int mt = 0; mt < 4; mt++) {
        int row0 = bm + warp_m * 64 + mt * 16 + gid;
        int row1 = row0 + 8;
#pragma unroll
        for (int nt = 0; nt < 4; nt++) {
            int col = bn + warp_n * 32 + nt * 8 + tig * 2;
            float b0 = 0.f, b1 = 0.f;
            if (BIAS) { b0 = bias[col]; b1 = bias[col + 1]; }
            float v0 = acc[mt][nt][0] + b0;
            float v1 = acc[mt][nt][1] + b1;
            float v2 = acc[mt][nt][2] + b0;
            float v3 = acc[mt][nt][3] + b1;
            if (RELU) {
                v0 = fmaxf(v0, 0.f); v1 = fmaxf(v1, 0.f);
                v2 = fmaxf(v2, 0.f); v3 = fmaxf(v3, 0.f);
            }
            *(float2*)(Cm + (size_t)row0 * N + col) = make_float2(v0, v1);
            *(float2*)(Cm + (size_t)row1 * N + col) = make_float2(v2, v3);
        }
    }
}

// ---------------------------------------------------------------------------
// Packed f32x2 helpers (sm_103a FFMA2 — PTX-only path)
// ---------------------------------------------------------------------------
typedef unsigned long long u64;

__device__ __forceinline__ u64 ffma2(u64 a, u64 b, u64 c)
{
    u64 d;
    asm("fma.rn.f32x2 %0, %1, %2, %3;" : "=l"(d) : "l"(a), "l"(b), "l"(c));
    return d;
}
__device__ __forceinline__ u64 fmul2(u64 a, u64 b)
{
    u64 d;
    asm("mul.rn.f32x2 %0, %1, %2;" : "=l"(d) : "l"(a), "l"(b));
    return d;
}
__device__ __forceinline__ u64 pack2(float lo, float hi)
{
    u64 d;
    asm("mov.b64 %0, {%1, %2};" : "=l"(d) : "f"(lo), "f"(hi));
    return d;
}
__device__ __forceinline__ float2 unpack2(u64 v)
{
    float lo, hi;
    asm("mov.b64 {%0, %1}, %2;" : "=f"(lo), "=f"(hi) : "l"(v));
    return make_float2(lo, hi);
}

// ---------------------------------------------------------------------------
// Flash-style causal attention with packed f32x2 math.
// Grid: (S/64, B*H). 64 threads, one query row per thread.
// ---------------------------------------------------------------------------
__global__ __launch_bounds__(64)
void attn_kernel(const float* __restrict__ Q, const float* __restrict__ Kt,
                 const float* __restrict__ Vt, float* __restrict__ O)
{
    const int qt  = blockIdx.x;
    const int bh  = blockIdx.y;
    const int b   = bh >> 4;
    const int h   = bh & (H_ - 1);
    const int tid = threadIdx.x;
    const int qs  = qt * 64 + tid;

    const size_t base = (size_t)b * S_ * C_ + (size_t)h * HD_;

    // Q row and accumulator as 32 packed f32x2
    u64 q2[32], acc2[32];
    const ulonglong2* qp = (const ulonglong2*)(Q + base + (size_t)qs * C_);
#pragma unroll
    for (int t = 0; t < 16; t++) {
        ulonglong2 v = qp[t];
        q2[2 * t]     = v.x;
        q2[2 * t + 1] = v.y;
        acc2[2 * t]     = 0ull;
        acc2[2 * t + 1] = 0ull;
    }

    float m = -1e30f, l = 0.f;
    const float scale = 0.125f;   // HD^-0.5

    __shared__ float4 KV4[64][16];
    __shared__ float  Ss[64][65];

    for (int jt = 0; jt <= qt; jt++) {
        // load K tile
        const float* kp = Kt + base + (size_t)(jt * 64) * C_;
        for (int r = 0; r < 64; r++)
            ((float*)&KV4[r][0])[tid] = kp[(size_t)r * C_ + tid];
        __syncthreads();

        const int jmax = (jt == qt) ? tid : 63;
        float mt = -1e30f;
        for (int j = 0; j <= jmax; j++) {
            const ulonglong2* kk = (const ulonglong2*)&KV4[j][0];
            // 4 independent packed accumulators to break the FMA chain
            u64 d0 = 0ull, d1 = 0ull, d2 = 0ull, d3 = 0ull;
#pragma unroll
            for (int t = 0; t < 4; t++) {
                ulonglong2 ka = kk[4 * t];
                ulonglong2 kb = kk[4 * t + 1];
                ulonglong2 kc = kk[4 * t + 2];
                ulonglong2 kd = kk[4 * t + 3];
                d0 = ffma2(q2[8 * t],     ka.x, d0);
                d1 = ffma2(q2[8 * t + 1], ka.y, d1);
                d2 = ffma2(q2[8 * t + 2], kb.x, d2);
                d3 = ffma2(q2[8 * t + 3], kb.y, d3);
                d0 = ffma2(q2[8 * t + 4], kc.x, d0);
                d1 = ffma2(q2[8 * t + 5], kc.y, d1);
                d2 = ffma2(q2[8 * t + 6], kd.x, d2);
                d3 = ffma2(q2[8 * t + 7], kd.y, d3);
            }
            float2 s0 = unpack2(d0), s1 = unpack2(d1);
            float2 s2 = unpack2(d2), s3 = unpack2(d3);
            float s = ((s0.x + s0.y) + (s1.x + s1.y)) +
                      ((s2.x + s2.y) + (s3.x + s3.y));
            s *= scale;
            Ss[tid][j] = s;
            mt = fmaxf(mt, s);
        }

        float mnew = fmaxf(m, mt);
        float corr = __expf(m - mnew);
        l *= corr;
        u64 corr2 = pack2(corr, corr);
#pragma unroll
        for (int i = 0; i < 32; i++)
            acc2[i] = fmul2(acc2[i], corr2);

        float ps = 0.f;
        for (int j = 0; j <= jmax; j++) {
            float p = __expf(Ss[tid][j] - mnew);
            Ss[tid][j] = p;
            ps += p;
        }
        l += ps;
        m = mnew;
        __syncthreads();

        // load V tile
        const float* vp = Vt + base + (size_t)(jt * 64) * C_;
        for (int r = 0; r < 64; r++)
            ((float*)&KV4[r][0])[tid] = vp[(size_t)r * C_ + tid];
        __syncthreads();

        for (int j = 0; j <= jmax; j++) {
            u64 pp = pack2(Ss[tid][j], Ss[tid][j]);
            const ulonglong2* vv = (const ulonglong2*)&KV4[j][0];
#pragma unroll
            for (int t = 0; t < 16; t++) {
                ulonglong2 v = vv[t];
                acc2[2 * t]     = ffma2(pp, v.x, acc2[2 * t]);
                acc2[2 * t + 1] = ffma2(pp, v.y, acc2[2 * t + 1]);
            }
        }
        __syncthreads();
    }

    const float inv = 1.f / l;
    float* op = O + base + (size_t)qs * C_;
#pragma unroll
    for (int i = 0; i < 32; i++) {
        float2 v = unpack2(acc2[i]);
        *(float2*)(op + 2 * i) = make_float2(v.x * inv, v.y * inv);
    }
}

// ---------------------------------------------------------------------------
// Launch
// ---------------------------------------------------------------------------
extern "C" void kernel_launch(void* const* d_in, const int* in_sizes, int n_in,
                              void* d_out, int out_size)
{
    const int*   idx   = (const int*)  d_in[0];
    const float* tok   = (const float*)d_in[1];
    const float* pos   = (const float*)d_in[2];
    const float* Wq    = (const float*)d_in[3];
    const float* Wk    = (const float*)d_in[4];
    const float* Wv    = (const float*)d_in[5];
    const float* Wproj = (const float*)d_in[6];
    const float* bproj = (const float*)d_in[7];
    const float* W1    = (const float*)d_in[8];
    const float* b1    = (const float*)d_in[9];
    const float* W2    = (const float*)d_in[10];
    const float* b2    = (const float*)d_in[11];
    const float* Wlm   = (const float*)d_in[12];
    const float* blm   = (const float*)d_in[13];
    float*       out   = (float*)d_out;

    float *x, *wq, *wk, *wv, *q, *k, *v, *o, *x2, *h1, *x3;
    cudaGetSymbolAddress((void**)&x,  g_x);
    cudaGetSymbolAddress((void**)&wq, g_wq);
    cudaGetSymbolAddress((void**)&wk, g_wk);
    cudaGetSymbolAddress((void**)&wv, g_wv);
    cudaGetSymbolAddress((void**)&q,  g_q);
    cudaGetSymbolAddress((void**)&k,  g_k);
    cudaGetSymbolAddress((void**)&v,  g_v);
    cudaGetSymbolAddress((void**)&o,  g_o);
    cudaGetSymbolAddress((void**)&x2, g_x2);
    cudaGetSymbolAddress((void**)&h1, g_h1);
    cudaGetSymbolAddress((void**)&x3, g_x3);

    // 1. pack QKV weights
    {
        int n = C_ * C_;
        pack_w_kernel<<<n / 256, 256>>>(Wq, wq);
        pack_w_kernel<<<n / 256, 256>>>(Wk, wk);
        pack_w_kernel<<<n / 256, 256>>>(Wv, wv);
    }

    // 2. embedding
    embed_kernel<<<(M_ * C_) / 256, 256>>>(idx, tok, pos, x);

    // 3. Q, K, V projections
    {
        dim3 grid(C_ / BN, M_ / BM);
        gemm_tf32_kernel<false, false><<<grid, 256>>>(x, wq, nullptr, q, M_, C_, C_);
        gemm_tf32_kernel<false, false><<<grid, 256>>>(x, wk, nullptr, k, M_, C_, C_);
        gemm_tf32_kernel<false, false><<<grid, 256>>>(x, wv, nullptr, v, M_, C_, C_);
    }

    // 4. causal attention
    {
        dim3 grid(S_ / 64, B_ * H_);
        attn_kernel<<<grid, 64>>>(q, k, v, o);
    }

    // 5. output projection
    {
        dim3 grid(C_ / BN, M_ / BM);
        gemm_tf32_kernel<false, true><<<grid, 256>>>(o, Wproj, bproj, x2, M_, C_, C_);
    }

    // 6. MLP
    {
        dim3 grid1(FF_ / BN, M_ / BM);
        gemm_tf32_kernel<true, true><<<grid1, 256>>>(x2, W1, b1, h1, M_, FF_, C_);
        dim3 grid2(C_ / BN, M_ / BM);
        gemm_tf32_kernel<false, true><<<grid2, 256>>>(h1, W2, b2, x3, M_, C_, FF_);
    }

    // 7. LM head
    {
        dim3 grid(V_ / BN, M_ / BM);
        gemm_tf32_kernel<false, true><<<grid, 256>>>(x3, Wlm, blm, out, M_, V_, C_);
    }
}